// round 8
// baseline (speedup 1.0000x reference)
#include <cuda_runtime.h>
#include <cuda_bf16.h>
#include <cstdint>

#define NUM_HEADS 4
#define DDIM      256
#define HID       512
#define NQ        256
#define TOPK      16
#define BN        128           // keys per score tile
#define NCL       148           // score-kernel CTAs
#define NCL2      (2*NCL)       // candidate lists per query (2 per CTA)
#define CAND      40            // rescore candidate pool per query

// ---- score-kernel dynamic smem layout (bytes) ----
#define A_OFF     0
#define A_BYTES   (256*512)             /* 256 q rows x 256 bf16 (swizzled) = 131072 */
#define B_OFF     A_BYTES
#define B_STAGE   (128*80)              /* 128 keys x 32 bf16, rows padded to 80B = 10240 */
#define S_OFF     (B_OFF + 2*B_STAGE)   /* 151552 */
#define S_STRIDE  68                    /* floats; 16B-aligned rows, conflict-free quad scan */
#define SMEM_SC   (S_OFF + 256*S_STRIDE*4)  /* 221184 */

// ---- device scratch (no allocations allowed) ----
__device__ __align__(16) float q_glob[NQ * DDIM];
__device__ float candS[(size_t)NQ * NCL2 * TOPK];
__device__ int   candI[(size_t)NQ * NCL2 * TOPK];

__device__ __forceinline__ uint32_t smem_u32(const void* p) {
    uint32_t a;
    asm("{ .reg .u64 t; cvta.to.shared.u64 t, %1; cvt.u32.u64 %0, t; }" : "=r"(a) : "l"(p));
    return a;
}
__device__ __forceinline__ float neg_inf() { return __int_as_float(0xff800000); }

#define LDSM_X4(r0,r1,r2,r3, addr) \
    asm volatile("ldmatrix.sync.aligned.m8n8.x4.shared.b16 {%0,%1,%2,%3}, [%4];" \
        : "=r"(r0), "=r"(r1), "=r"(r2), "=r"(r3) : "r"(addr))
#define MMA_BF16(d, a, b) \
    asm volatile("mma.sync.aligned.m16n8k16.row.col.f32.bf16.bf16.f32 " \
        "{%0,%1,%2,%3}, {%4,%5,%6,%7}, {%8,%9}, {%0,%1,%2,%3};" \
        : "+f"((d)[0]), "+f"((d)[1]), "+f"((d)[2]), "+f"((d)[3]) \
        : "r"((a)[0]), "r"((a)[1]), "r"((a)[2]), "r"((a)[3]), "r"((b)[0]), "r"((b)[1]))

__device__ __forceinline__ uint32_t pack_bf16x2(float lo, float hi) {
    __nv_bfloat162 h = __floats2bfloat162_rn(lo, hi);
    return *reinterpret_cast<uint32_t*>(&h);
}

// sorted top-16 insert (descending; tie -> smaller index first)
__device__ __forceinline__ void ins16(float s, int key, float* topS, int* topI) {
    if (s > topS[TOPK - 1] || (s == topS[TOPK - 1] && key < topI[TOPK - 1])) {
        float cs = s; int ci = key;
#pragma unroll
        for (int p = 0; p < TOPK; ++p) {
            bool sw = (cs > topS[p]) || (cs == topS[p] && ci < topI[p]);
            float ts = topS[p]; int ti = topI[p];
            topS[p] = sw ? cs : ts;  topI[p] = sw ? ci : ti;
            cs = sw ? ts : cs;       ci = sw ? ti : ci;
        }
    }
}

// =====================================================================
// Kernel 1: q = layer_norm(hidden @ Wp + bp) -> q_glob [256,256]
// grid 64 (batch rows), 256 threads; thread t owns 4 consecutive cols
// (float4 loads on Wp). LN reduction per head = 2 warps via shuffle+smem.
// =====================================================================
__global__ void proj_ln_kernel(const float* __restrict__ hidden,
                               const float* __restrict__ Wp,
                               const float* __restrict__ bp) {
    __shared__ float hid[HID];
    __shared__ float wsum[8], wsq[8];
    int b = blockIdx.x, t = threadIdx.x, lane = t & 31, wid = t >> 5;

    hid[t]       = hidden[b * HID + t];
    hid[t + 256] = hidden[b * HID + 256 + t];
    __syncthreads();

    const float4* W4 = reinterpret_cast<const float4*>(Wp);   // [512][256]
    float4 acc = make_float4(0.f, 0.f, 0.f, 0.f);
#pragma unroll 8
    for (int k = 0; k < HID; ++k) {
        float4 w = W4[k * 256 + t];
        float hk = hid[k];
        acc.x = fmaf(hk, w.x, acc.x); acc.y = fmaf(hk, w.y, acc.y);
        acc.z = fmaf(hk, w.z, acc.z); acc.w = fmaf(hk, w.w, acc.w);
    }
    float4 bias = reinterpret_cast<const float4*>(bp)[t];
    float4 x = make_float4(acc.x + bias.x, acc.y + bias.y,
                           acc.z + bias.z, acc.w + bias.w);

    float s1 = x.x + x.y + x.z + x.w;
    float s2 = x.x*x.x + x.y*x.y + x.z*x.z + x.w*x.w;
#pragma unroll
    for (int o = 16; o; o >>= 1) {
        s1 += __shfl_xor_sync(0xffffffffu, s1, o);
        s2 += __shfl_xor_sync(0xffffffffu, s2, o);
    }
    if (lane == 0) { wsum[wid] = s1; wsq[wid] = s2; }
    __syncthreads();

    int h = t >> 6;                         // head (64 threads = 256 cols)
    float hs1 = wsum[2*h] + wsum[2*h + 1];
    float hs2 = wsq [2*h] + wsq [2*h + 1];
    float mean = hs1 * (1.0f / DDIM);
    float var  = hs2 * (1.0f / DDIM) - mean * mean;
    float r = rsqrtf(var + 1e-5f);

    float4 o4 = make_float4((x.x - mean) * r, (x.y - mean) * r,
                            (x.z - mean) * r, (x.w - mean) * r);
    reinterpret_cast<float4*>(q_glob)[(h * 64 + b) * 64 + (t & 63)] = o4;
}

// =====================================================================
// Kernel 2: bf16 mma.sync score GEMM fused with per-thread top-16.
// 512 threads / 16 warps. Block tile 256q x 128k, K in 8 stages of 32.
// Warp tile 64x32: wm = wid&3 (64 q-rows), wn = wid>>2 (32 key-cols).
// A resident bf16 smem (XOR swizzle); B double-buffered LDG->cvt->STS.
// Next-tile stage-0 prefetch overlaps the epilogue. Epilogue: two
// 64-col halves through smem S; 2 threads per query, float4 scan with
// cached-threshold gate; 2 top-16 lists per query per CTA.
// =====================================================================
__global__ void __launch_bounds__(512, 1)
score_kernel(const float* __restrict__ mem, int nkeys, int ntiles) {
    extern __shared__ __align__(16) char smem[];
    uint32_t sb = smem_u32(smem);
    int tid = threadIdx.x, lane = tid & 31, wid = tid >> 5;
    int wm = wid & 3, wn = wid >> 2;

    // ---- fill A (bf16, swizzled) from q_glob ----
#pragma unroll 4
    for (int idx = tid; idx < 256 * 128; idx += 512) {
        int m = idx >> 7, kp = idx & 127;
        float2 v = *reinterpret_cast<const float2*>(q_glob + m * DDIM + 2 * kp);
        uint32_t off = (uint32_t)(A_OFF + m * 512 + ((kp * 4) ^ ((m & 7) << 4)));
        *reinterpret_cast<uint32_t*>(smem + off) = pack_bf16x2(v.x, v.y);
    }
    __syncthreads();

    // ---- per-thread invariants ----
    int ldrow = tid >> 2;                  // B-load: key row in tile (0..127)
    int ldk   = (tid & 3) * 8;             // B-load: k sub-chunk (floats)
    uint32_t sts_base = (uint32_t)(B_OFF + ldrow * 80 + (tid & 3) * 16);

    uint32_t a_rowbyte = (uint32_t)(A_OFF + (wm * 64 + (lane & 15)) * 512);
    uint32_t a_swz   = (uint32_t)((lane & 7) << 4);
    uint32_t a_koff2 = (uint32_t)((lane >> 4) * 16);     // bytes
    int sub = lane >> 3;
    uint32_t b_lane = (uint32_t)(((wn * 32 + (sub >> 1) * 8 + (lane & 7)) * 80) +
                                 ((sub & 1) * 8) * 2);

    float topS[TOPK]; int topI[TOPK];
#pragma unroll
    for (int i = 0; i < TOPK; ++i) { topS[i] = neg_inf(); topI[i] = 0x7fffffff; }
    float thr = neg_inf(); int thrI = 0x7fffffff;

    // prefetch tile 0, stage 0
    float4 pf[2];
    {
        int key = blockIdx.x * BN + ldrow;
        if (key < nkeys) {
            const float4* src = reinterpret_cast<const float4*>(
                mem + (size_t)key * DDIM + ldk);
            pf[0] = src[0]; pf[1] = src[1];
        } else {
            pf[0] = pf[1] = make_float4(0.f, 0.f, 0.f, 0.f);
        }
    }

    for (int tile = blockIdx.x; tile < ntiles; tile += NCL) {
        int keybase = tile * BN;
        float acc[4][4][4];
#pragma unroll
        for (int mt = 0; mt < 4; ++mt)
#pragma unroll
            for (int nt = 0; nt < 4; ++nt)
#pragma unroll
                for (int e = 0; e < 4; ++e) acc[mt][nt][e] = 0.f;

#pragma unroll 1
        for (int s = 0; s < 8; ++s) {
            int buf = s & 1;
            // convert + STS current stage
            {
                uint4 u;
                u.x = pack_bf16x2(pf[0].x, pf[0].y);
                u.y = pack_bf16x2(pf[0].z, pf[0].w);
                u.z = pack_bf16x2(pf[1].x, pf[1].y);
                u.w = pack_bf16x2(pf[1].z, pf[1].w);
                *reinterpret_cast<uint4*>(smem + sts_base + buf * B_STAGE) = u;
            }
            __syncthreads();
            // prefetch next stage (or next tile's stage 0)
            {
                int nt2 = (s < 7) ? tile : tile + NCL;
                int koff = (s < 7) ? (s + 1) * 32 : 0;
                int key = nt2 * BN + ldrow;
                if (nt2 < ntiles && key < nkeys) {
                    const float4* src = reinterpret_cast<const float4*>(
                        mem + (size_t)key * DDIM + koff + ldk);
                    pf[0] = src[0]; pf[1] = src[1];
                } else {
                    pf[0] = pf[1] = make_float4(0.f, 0.f, 0.f, 0.f);
                }
            }
            // mma over this stage (2 x k16)
            uint32_t bbuf = sb + (uint32_t)(B_OFF + buf * B_STAGE);
#pragma unroll
            for (int kk = 0; kk < 2; ++kk) {
                uint32_t kbyte = (uint32_t)((s * 32 + kk * 16) * 2);
                uint32_t a[4][4];
#pragma unroll
                for (int mt = 0; mt < 4; ++mt)
                    LDSM_X4(a[mt][0], a[mt][1], a[mt][2], a[mt][3],
                            sb + a_rowbyte + (uint32_t)(mt * 8192) +
                            ((kbyte + a_koff2) ^ a_swz));
                uint32_t b[4][2];
#pragma unroll
                for (int p = 0; p < 2; ++p)
                    LDSM_X4(b[2*p][0], b[2*p][1], b[2*p+1][0], b[2*p+1][1],
                            bbuf + b_lane + (uint32_t)(p * 1280 + kk * 32));
#pragma unroll
                for (int mt = 0; mt < 4; ++mt)
#pragma unroll
                    for (int nt = 0; nt < 4; ++nt)
                        MMA_BF16(acc[mt][nt], a[mt], b[nt]);
            }
        }

        // ---- epilogue: two 64-col halves; warps wn in {2h,2h+1} write ----
        float* S = reinterpret_cast<float*>(smem + S_OFF);
        int colbase = (tid >> 8) * 32;          // this thread's 32-col slice
        int q = tid & 255;
#pragma unroll 1
        for (int half = 0; half < 2; ++half) {
            if ((wn >> 1) == half) {
                int cb = (wn & 1) * 32;
#pragma unroll
                for (int mt = 0; mt < 4; ++mt) {
                    int row = wm * 64 + mt * 16 + (lane >> 2);
#pragma unroll
                    for (int nt = 0; nt < 4; ++nt) {
                        int col = cb + nt * 8 + (lane & 3) * 2;
                        S[row * S_STRIDE + col]           = acc[mt][nt][0];
                        S[row * S_STRIDE + col + 1]       = acc[mt][nt][1];
                        S[(row + 8) * S_STRIDE + col]     = acc[mt][nt][2];
                        S[(row + 8) * S_STRIDE + col + 1] = acc[mt][nt][3];
                    }
                }
            }
            __syncthreads();
            int kb = keybase + half * 64 + colbase;
            const float* srow = S + q * S_STRIDE + colbase;
            if (keybase + BN <= nkeys) {
                // fast path: quad loads + threshold gate
#pragma unroll 2
                for (int j4 = 0; j4 < 8; ++j4) {
                    float4 v = *reinterpret_cast<const float4*>(srow + 4 * j4);
                    float m = fmaxf(fmaxf(v.x, v.y), fmaxf(v.z, v.w));
                    if (m >= thr) {
                        int k0 = kb + 4 * j4;
                        ins16(v.x, k0,     topS, topI);
                        ins16(v.y, k0 + 1, topS, topI);
                        ins16(v.z, k0 + 2, topS, topI);
                        ins16(v.w, k0 + 3, topS, topI);
                        thr = topS[TOPK - 1]; thrI = topI[TOPK - 1];
                    }
                }
            } else {
                for (int j = 0; j < 32; ++j) {
                    int key = kb + j;
                    if (key >= nkeys) break;
                    float sc = srow[j];
                    if (sc > thr || (sc == thr && key < thrI)) {
                        ins16(sc, key, topS, topI);
                        thr = topS[TOPK - 1]; thrI = topI[TOPK - 1];
                    }
                }
            }
            __syncthreads();
        }
    }

    // ---- emit sorted candidate lists: 2 per query per CTA ----
    {
        int q = tid & 255, sub2 = tid >> 8;
        size_t base = ((size_t)q * NCL2 + blockIdx.x * 2 + sub2) * TOPK;
#pragma unroll
        for (int i = 0; i < TOPK; ++i) { candS[base + i] = topS[i]; candI[base + i] = topI[i]; }
    }
}

// =====================================================================
// Kernel 3: merge 296 sorted candidate lists -> top-40, exact fp32
// rescore, final top-16 + gather. block = query, 128 threads.
// =====================================================================
__global__ void merge_rescore_kernel(const float* __restrict__ mem,
                                     float* __restrict__ out, int nkeys) {
    __shared__ float ls[32 * TOPK];
    __shared__ int   li[32 * TOPK];
    __shared__ float csm[CAND];
    __shared__ int   cim[CAND];
    __shared__ float qrow[DDIM];
    __shared__ float rs[CAND];
    __shared__ float fs[TOPK];
    __shared__ int   fi[TOPK];

    int q = blockIdx.x, t = threadIdx.x;   // 128 threads
    qrow[t]       = q_glob[q * DDIM + t];
    qrow[t + 128] = q_glob[q * DDIM + 128 + t];

    if (t < 32) {
        float bs[TOPK]; int bi[TOPK];
#pragma unroll
        for (int i = 0; i < TOPK; ++i) { bs[i] = neg_inf(); bi[i] = 0x7fffffff; }
        for (int cl = t; cl < NCL2; cl += 32) {
            size_t base = ((size_t)q * NCL2 + cl) * TOPK;
#pragma unroll 1
            for (int i = 0; i < TOPK; ++i) {
                float s = candS[base + i]; int id = candI[base + i];
                if (!(s > bs[TOPK - 1] || (s == bs[TOPK - 1] && id < bi[TOPK - 1]))) break;
                float cs = s; int ci = id;
#pragma unroll
                for (int p = 0; p < TOPK; ++p) {
                    bool sw = (cs > bs[p]) || (cs == bs[p] && ci < bi[p]);
                    if (sw) { float ts = bs[p]; int ti = bi[p];
                              bs[p] = cs; bi[p] = ci; cs = ts; ci = ti; }
                }
            }
        }
#pragma unroll
        for (int i = 0; i < TOPK; ++i) { ls[t * TOPK + i] = bs[i]; li[t * TOPK + i] = bi[i]; }
    }
    __syncthreads();

    if (t == 0) {
        for (int i = 0; i < CAND; ++i) { csm[i] = neg_inf(); cim[i] = 0x7fffffff; }
        for (int l = 0; l < 32; ++l) {
#pragma unroll 1
            for (int i = 0; i < TOPK; ++i) {
                float s = ls[l * TOPK + i]; int id = li[l * TOPK + i];
                if (!(s > csm[CAND - 1] || (s == csm[CAND - 1] && id < cim[CAND - 1]))) break;
                int p = CAND - 1;
                while (p > 0 && (s > csm[p - 1] || (s == csm[p - 1] && id < cim[p - 1]))) {
                    csm[p] = csm[p - 1]; cim[p] = cim[p - 1]; --p;
                }
                csm[p] = s; cim[p] = id;
            }
        }
    }
    __syncthreads();

    // exact fp32 rescore; warp w handles candidates w, w+4, ...
    {
        int w = t >> 5, l = t & 31;
        for (int k = w; k < CAND; k += 4) {
            int id = cim[k];
            float sum = 0.f;
            if (id >= 0 && id < nkeys) {
                const float* row = mem + (size_t)id * DDIM;
#pragma unroll
                for (int d = l; d < DDIM; d += 32) sum = fmaf(qrow[d], row[d], sum);
            }
#pragma unroll
            for (int o = 16; o; o >>= 1) sum += __shfl_xor_sync(0xffffffffu, sum, o);
            if (l == 0) rs[k] = (id >= 0 && id < nkeys) ? sum : neg_inf();
        }
    }
    __syncthreads();

    if (t == 0) {
        float bs[TOPK]; int bi[TOPK];
#pragma unroll
        for (int i = 0; i < TOPK; ++i) { bs[i] = neg_inf(); bi[i] = 0x7fffffff; }
        for (int k = 0; k < CAND; ++k) {
            float s = rs[k]; int id = cim[k];
            if (s > bs[TOPK - 1] || (s == bs[TOPK - 1] && id < bi[TOPK - 1])) {
                float cs = s; int ci = id;
#pragma unroll
                for (int p = 0; p < TOPK; ++p) {
                    bool sw = (cs > bs[p]) || (cs == bs[p] && ci < bi[p]);
                    if (sw) { float ts = bs[p]; int ti = bi[p];
                              bs[p] = cs; bi[p] = ci; cs = ts; ci = ti; }
                }
            }
        }
#pragma unroll
        for (int i = 0; i < TOPK; ++i) { fs[i] = bs[i]; fi[i] = bi[i]; }
    }
    __syncthreads();

    if (t < TOPK) {
        out[q * TOPK + t]             = fs[t];
        out[NQ * TOPK + q * TOPK + t] = (float)fi[t];
    }
#pragma unroll 1
    for (int i = 0; i < TOPK; ++i) {
        int row = fi[i];
        size_t ob = (size_t)2 * NQ * TOPK + ((size_t)(q * TOPK + i)) * DDIM;
        out[ob + t]       = mem[(size_t)row * DDIM + t];
        out[ob + 128 + t] = mem[(size_t)row * DDIM + 128 + t];
    }
}

// =====================================================================
extern "C" void kernel_launch(void* const* d_in, const int* in_sizes, int n_in,
                              void* d_out, int out_size) {
    const float* hidden = (const float*)d_in[0];   // [64, 512]
    const float* Wp     = (const float*)d_in[1];   // [512, 1024]
    const float* bp     = (const float*)d_in[2];   // [1024]
    const float* mem    = (const float*)d_in[3];   // [N, 256]
    int nkeys  = in_sizes[3] / DDIM;
    int ntiles = (nkeys + BN - 1) / BN;

    proj_ln_kernel<<<64, 256>>>(hidden, Wp, bp);

    cudaFuncSetAttribute(score_kernel, cudaFuncAttributeMaxDynamicSharedMemorySize,
                         SMEM_SC);
    score_kernel<<<NCL, 512, SMEM_SC>>>(mem, nkeys, ntiles);

    merge_rescore_kernel<<<NQ, 128>>>(mem, (float*)d_out, nkeys);
}

// round 10
// speedup vs baseline: 1.0039x; 1.0039x over previous
#include <cuda_runtime.h>
#include <cuda_bf16.h>
#include <cstdint>

#define NUM_HEADS 4
#define DDIM      256
#define HID       512
#define NQ        256
#define TOPK      16
#define BN        128           // keys per score tile
#define NCL       148           // score-kernel CTAs (= candidate lists/query)
#define CAND      64            // rescore candidate pool per query

// ---- score-kernel dynamic smem layout (bytes) ----
#define A_OFF     0
#define A_BYTES   (256*256)             /* 256 q rows x 256 fp8 (swizzled) = 65536 */
#define B_OFF     A_BYTES
#define B_STAGE   (128*48)              /* 128 keys x 32 fp8, rows padded to 48B = 6144 */
#define S_OFF     (B_OFF + 2*B_STAGE)   /* 77824 */
#define S_STRIDE  136                   /* floats; 16B-aligned rows */
#define SMEM_SC   (S_OFF + 256*S_STRIDE*4)  /* 217088 */

// ---- device scratch (no allocations allowed) ----
__device__ __align__(16) float q_glob[NQ * DDIM];
__device__ float candS[(size_t)NQ * NCL * TOPK];
__device__ int   candI[(size_t)NQ * NCL * TOPK];

__device__ __forceinline__ uint32_t smem_u32(const void* p) {
    uint32_t a;
    asm("{ .reg .u64 t; cvta.to.shared.u64 t, %1; cvt.u32.u64 %0, t; }" : "=r"(a) : "l"(p));
    return a;
}
__device__ __forceinline__ float neg_inf() { return __int_as_float(0xff800000); }

#define LDSM_X4(r0,r1,r2,r3, addr) \
    asm volatile("ldmatrix.sync.aligned.m8n8.x4.shared.b16 {%0,%1,%2,%3}, [%4];" \
        : "=r"(r0), "=r"(r1), "=r"(r2), "=r"(r3) : "r"(addr))

// fp8 e4m3 mma: D(16x8,f32) += A(16x32) * B(32x8)
#define MMA_FP8(d, a, b) \
    asm volatile("mma.sync.aligned.m16n8k32.row.col.f32.e4m3.e4m3.f32 " \
        "{%0,%1,%2,%3}, {%4,%5,%6,%7}, {%8,%9}, {%0,%1,%2,%3};" \
        : "+f"((d)[0]), "+f"((d)[1]), "+f"((d)[2]), "+f"((d)[3]) \
        : "r"((a)[0]), "r"((a)[1]), "r"((a)[2]), "r"((a)[3]), "r"((b)[0]), "r"((b)[1]))

// pack 4 floats -> 4 e4m3 bytes (x in lowest byte).
// cvt.rn.satfinite.e4m3x2.f32 d, a, b  => 16-bit dest, b -> low byte.
__device__ __forceinline__ uint32_t pack_e4m3x4(float x, float y, float z, float w) {
    uint16_t lo, hi; uint32_t r;
    asm("cvt.rn.satfinite.e4m3x2.f32 %0, %1, %2;" : "=h"(lo) : "f"(y), "f"(x));
    asm("cvt.rn.satfinite.e4m3x2.f32 %0, %1, %2;" : "=h"(hi) : "f"(w), "f"(z));
    asm("mov.b32 %0, {%1, %2};" : "=r"(r) : "h"(lo), "h"(hi));
    return r;
}

// sorted top-16 insert (descending; tie -> smaller index first)
__device__ __forceinline__ void ins16(float s, int key, float* topS, int* topI) {
    if (s > topS[TOPK - 1] || (s == topS[TOPK - 1] && key < topI[TOPK - 1])) {
        float cs = s; int ci = key;
#pragma unroll
        for (int p = 0; p < TOPK; ++p) {
            bool sw = (cs > topS[p]) || (cs == topS[p] && ci < topI[p]);
            float ts = topS[p]; int ti = topI[p];
            topS[p] = sw ? cs : ts;  topI[p] = sw ? ci : ti;
            cs = sw ? ts : cs;       ci = sw ? ti : ci;
        }
    }
}

// =====================================================================
// Kernel 1: q = layer_norm(hidden @ Wp + bp) -> q_glob [256,256]
// grid 256 = (batch b = bid>>2, head h = bid&3); 256 threads:
// colquad cq = t&63 (4 cols), kslice ks = t>>6 (128 k each). Coalesced
// float4 Wp reads, smem partial reduce, 2-warp LN reduction.
// =====================================================================
__global__ void proj_ln_kernel(const float* __restrict__ hidden,
                               const float* __restrict__ Wp,
                               const float* __restrict__ bp) {
    __shared__ float hid[HID];
    __shared__ float4 part[256];
    __shared__ float red1[2], red2[2];
    int b = blockIdx.x >> 2, h = blockIdx.x & 3;
    int t = threadIdx.x, lane = t & 31;
    int cq = t & 63, ks = t >> 6;

    hid[t]       = hidden[b * HID + t];
    hid[t + 256] = hidden[b * HID + 256 + t];
    __syncthreads();

    const float4* W4 = reinterpret_cast<const float4*>(Wp);   // rows of 256 float4
    float4 acc = make_float4(0.f, 0.f, 0.f, 0.f);
    int kbase = ks * 128;
#pragma unroll 8
    for (int k = 0; k < 128; ++k) {
        float4 w = W4[(size_t)(kbase + k) * 256 + h * 64 + cq];
        float hk = hid[kbase + k];
        acc.x = fmaf(hk, w.x, acc.x); acc.y = fmaf(hk, w.y, acc.y);
        acc.z = fmaf(hk, w.z, acc.z); acc.w = fmaf(hk, w.w, acc.w);
    }
    part[t] = acc;
    __syncthreads();

    float4 x;
    float s1 = 0.f, s2 = 0.f;
    if (t < 64) {
        float4 a0 = part[t], a1 = part[64 + t], a2 = part[128 + t], a3 = part[192 + t];
        float4 bias = reinterpret_cast<const float4*>(bp)[h * 64 + t];
        x = make_float4(a0.x + a1.x + a2.x + a3.x + bias.x,
                        a0.y + a1.y + a2.y + a3.y + bias.y,
                        a0.z + a1.z + a2.z + a3.z + bias.z,
                        a0.w + a1.w + a2.w + a3.w + bias.w);
        s1 = x.x + x.y + x.z + x.w;
        s2 = x.x * x.x + x.y * x.y + x.z * x.z + x.w * x.w;
#pragma unroll
        for (int o = 16; o; o >>= 1) {
            s1 += __shfl_xor_sync(0xffffffffu, s1, o);
            s2 += __shfl_xor_sync(0xffffffffu, s2, o);
        }
        if (lane == 0) { red1[t >> 5] = s1; red2[t >> 5] = s2; }
    }
    __syncthreads();
    if (t < 64) {
        float hs1 = red1[0] + red1[1], hs2 = red2[0] + red2[1];
        float mean = hs1 * (1.0f / DDIM);
        float var  = hs2 * (1.0f / DDIM) - mean * mean;
        float r = rsqrtf(var + 1e-5f);
        float4 o4 = make_float4((x.x - mean) * r, (x.y - mean) * r,
                                (x.z - mean) * r, (x.w - mean) * r);
        reinterpret_cast<float4*>(q_glob)[(size_t)(h * 64 + b) * 64 + t] = o4;
    }
}

// =====================================================================
// Kernel 2: fp8 e4m3 mma.sync score GEMM fused with per-query top-16.
// 256 threads / 8 warps. Block tile 256q x 128k; K in 8 stages of 32.
// Warp tile 64x64: wm = wid&3 (q rows), wn = wid>>2 (0/1, key cols).
// A resident fp8 smem (XOR swizzle); B double-buffered LDG(fp32)->
// cvt(e4m3)->STS (48B rows). One k32 mma-iter per stage. Epilogue:
// full 256x128 fp32 score tile in smem, one sync, gated float4 scan,
// thread = query; candidates fixed exactly by fp32 rescore of top-64.
// =====================================================================
__global__ void __launch_bounds__(256, 1)
score_kernel(const float* __restrict__ mem, int nkeys, int ntiles) {
    extern __shared__ __align__(16) char smem[];
    uint32_t sb = smem_u32(smem);
    int tid = threadIdx.x, lane = tid & 31, wid = tid >> 5;
    int wm = wid & 3, wn = wid >> 2;

    // ---- fill A (fp8, swizzled) from q_glob ----
#pragma unroll 4
    for (int idx = tid; idx < 256 * 64; idx += 256) {
        int m = idx >> 6, cq = idx & 63;
        float4 v = reinterpret_cast<const float4*>(q_glob)[m * 64 + cq];
        uint32_t off = (uint32_t)(A_OFF + m * 256 + ((cq * 4) ^ ((m & 7) << 4)));
        *reinterpret_cast<uint32_t*>(smem + off) = pack_e4m3x4(v.x, v.y, v.z, v.w);
    }
    __syncthreads();

    // ---- per-thread invariants ----
    int ldrow = tid >> 1;                  // B-load: key row in tile (0..127)
    int ldk   = (tid & 1) * 16;            // B-load: k sub-chunk (floats)
    uint32_t sts_base = (uint32_t)(B_OFF + ldrow * 48 + (tid & 1) * 16);

    uint32_t a_row  = (uint32_t)(wm * 64 + (lane & 15));
    uint32_t a_base = (uint32_t)(A_OFF) + a_row * 256;
    uint32_t a_k16  = (uint32_t)((lane >> 4) * 16);
    uint32_t a_sw   = (a_row & 7) << 4;

    int sub = lane >> 3;
    uint32_t b_row  = (uint32_t)(wn * 64 + (sub >> 1) * 8 + (lane & 7));
    uint32_t b_koff = (uint32_t)((sub & 1) * 16);

    float topS[TOPK]; int topI[TOPK];
#pragma unroll
    for (int i = 0; i < TOPK; ++i) { topS[i] = neg_inf(); topI[i] = 0x7fffffff; }
    float thr = neg_inf(); int thrI = 0x7fffffff;

    // prefetch tile 0, stage 0 (16 floats / thread)
    float4 pf[4];
    {
        int key = blockIdx.x * BN + ldrow;
        if (key < nkeys) {
            const float4* src = reinterpret_cast<const float4*>(
                mem + (size_t)key * DDIM + ldk);
#pragma unroll
            for (int v = 0; v < 4; ++v) pf[v] = src[v];
        } else {
#pragma unroll
            for (int v = 0; v < 4; ++v) pf[v] = make_float4(0.f, 0.f, 0.f, 0.f);
        }
    }

    for (int tile = blockIdx.x; tile < ntiles; tile += NCL) {
        int keybase = tile * BN;
        float acc[4][8][4];
#pragma unroll
        for (int mt = 0; mt < 4; ++mt)
#pragma unroll
            for (int nt = 0; nt < 8; ++nt)
#pragma unroll
                for (int e = 0; e < 4; ++e) acc[mt][nt][e] = 0.f;

#pragma unroll 1
        for (int s = 0; s < 8; ++s) {
            int buf = s & 1;
            // convert + STS current stage (16 fp8 per thread)
            {
                uint4 u;
                u.x = pack_e4m3x4(pf[0].x, pf[0].y, pf[0].z, pf[0].w);
                u.y = pack_e4m3x4(pf[1].x, pf[1].y, pf[1].z, pf[1].w);
                u.z = pack_e4m3x4(pf[2].x, pf[2].y, pf[2].z, pf[2].w);
                u.w = pack_e4m3x4(pf[3].x, pf[3].y, pf[3].z, pf[3].w);
                *reinterpret_cast<uint4*>(smem + sts_base + buf * B_STAGE) = u;
            }
            __syncthreads();
            // prefetch next stage (or next tile's stage 0)
            {
                int nt2 = (s < 7) ? tile : tile + NCL;
                int koff = (s < 7) ? (s + 1) * 32 : 0;
                int key = nt2 * BN + ldrow;
                if (nt2 < ntiles && key < nkeys) {
                    const float4* src = reinterpret_cast<const float4*>(
                        mem + (size_t)key * DDIM + koff + ldk);
#pragma unroll
                    for (int v = 0; v < 4; ++v) pf[v] = src[v];
                } else {
#pragma unroll
                    for (int v = 0; v < 4; ++v) pf[v] = make_float4(0.f, 0.f, 0.f, 0.f);
                }
            }
            // mma: one k32 iteration for this stage
            uint32_t bbuf = sb + (uint32_t)(B_OFF + buf * B_STAGE);
            uint32_t kbyte = (uint32_t)(s * 32);
            uint32_t bfr[8][2];
#pragma unroll
            for (int p = 0; p < 4; ++p)
                LDSM_X4(bfr[2*p][0], bfr[2*p][1], bfr[2*p+1][0], bfr[2*p+1][1],
                        bbuf + (b_row + (uint32_t)(p * 16)) * 48 + b_koff);
#pragma unroll
            for (int mt = 0; mt < 4; ++mt) {
                uint32_t a[4];
                LDSM_X4(a[0], a[1], a[2], a[3],
                        sb + a_base + (uint32_t)(mt * 16 * 256) +
                        ((kbyte + a_k16) ^ a_sw));
#pragma unroll
                for (int nt = 0; nt < 8; ++nt)
                    MMA_FP8(acc[mt][nt], a, bfr[nt]);
            }
        }

        // ---- epilogue: full 256 x 128 score tile, one sync, gated scan ----
        float* S = reinterpret_cast<float*>(smem + S_OFF);
        {
            int cb = wn * 64;
#pragma unroll
            for (int mt = 0; mt < 4; ++mt) {
                int row = wm * 64 + mt * 16 + (lane >> 2);
#pragma unroll
                for (int nt = 0; nt < 8; ++nt) {
                    int col = cb + nt * 8 + (lane & 3) * 2;
                    S[row * S_STRIDE + col]           = acc[mt][nt][0];
                    S[row * S_STRIDE + col + 1]       = acc[mt][nt][1];
                    S[(row + 8) * S_STRIDE + col]     = acc[mt][nt][2];
                    S[(row + 8) * S_STRIDE + col + 1] = acc[mt][nt][3];
                }
            }
        }
        __syncthreads();
        {
            const float* srow = S + tid * S_STRIDE;
            if (keybase + BN <= nkeys) {
#pragma unroll 2
                for (int j4 = 0; j4 < 32; ++j4) {
                    float4 v = *reinterpret_cast<const float4*>(srow + 4 * j4);
                    float m = fmaxf(fmaxf(v.x, v.y), fmaxf(v.z, v.w));
                    if (m >= thr) {
                        int k0 = keybase + 4 * j4;
                        ins16(v.x, k0,     topS, topI);
                        ins16(v.y, k0 + 1, topS, topI);
                        ins16(v.z, k0 + 2, topS, topI);
                        ins16(v.w, k0 + 3, topS, topI);
                        thr = topS[TOPK - 1]; thrI = topI[TOPK - 1];
                    }
                }
            } else {
                for (int j = 0; j < BN; ++j) {
                    int key = keybase + j;
                    if (key >= nkeys) break;
                    float sc = srow[j];
                    if (sc > thr || (sc == thr && key < thrI)) {
                        ins16(sc, key, topS, topI);
                        thr = topS[TOPK - 1]; thrI = topI[TOPK - 1];
                    }
                }
            }
        }
        // no sync needed here: S is next written only after 8 stage-syncs
    }

    // ---- emit per-CTA sorted candidate list (thread = query) ----
    size_t base = ((size_t)tid * NCL + blockIdx.x) * TOPK;
#pragma unroll
    for (int i = 0; i < TOPK; ++i) { candS[base + i] = topS[i]; candI[base + i] = topI[i]; }
}

// =====================================================================
// Kernel 3: merge 148 sorted fp8-score candidate lists -> top-64,
// exact fp32 rescore, final top-16 + gather. block = query, 128 threads.
// =====================================================================
__global__ void merge_rescore_kernel(const float* __restrict__ mem,
                                     float* __restrict__ out, int nkeys) {
    __shared__ float ls[32 * TOPK];
    __shared__ int   li[32 * TOPK];
    __shared__ float csm[CAND];
    __shared__ int   cim[CAND];
    __shared__ float qrow[DDIM];
    __shared__ float rs[CAND];
    __shared__ float fs[TOPK];
    __shared__ int   fi[TOPK];

    int q = blockIdx.x, t = threadIdx.x;   // 128 threads
    qrow[t]       = q_glob[q * DDIM + t];
    qrow[t + 128] = q_glob[q * DDIM + 128 + t];

    if (t < 32) {
        float bs[TOPK]; int bi[TOPK];
#pragma unroll
        for (int i = 0; i < TOPK; ++i) { bs[i] = neg_inf(); bi[i] = 0x7fffffff; }
        for (int cl = t; cl < NCL; cl += 32) {
            size_t base = ((size_t)q * NCL + cl) * TOPK;
#pragma unroll 1
            for (int i = 0; i < TOPK; ++i) {
                float s = candS[base + i]; int id = candI[base + i];
                if (!(s > bs[TOPK - 1] || (s == bs[TOPK - 1] && id < bi[TOPK - 1]))) break;
                float cs = s; int ci = id;
#pragma unroll
                for (int p = 0; p < TOPK; ++p) {
                    bool sw = (cs > bs[p]) || (cs == bs[p] && ci < bi[p]);
                    if (sw) { float ts = bs[p]; int ti = bi[p];
                              bs[p] = cs; bi[p] = ci; cs = ts; ci = ti; }
                }
            }
        }
#pragma unroll
        for (int i = 0; i < TOPK; ++i) { ls[t * TOPK + i] = bs[i]; li[t * TOPK + i] = bi[i]; }
    }
    __syncthreads();

    if (t == 0) {
        for (int i = 0; i < CAND; ++i) { csm[i] = neg_inf(); cim[i] = 0x7fffffff; }
        for (int l = 0; l < 32; ++l) {
#pragma unroll 1
            for (int i = 0; i < TOPK; ++i) {
                float s = ls[l * TOPK + i]; int id = li[l * TOPK + i];
                if (!(s > csm[CAND - 1] || (s == csm[CAND - 1] && id < cim[CAND - 1]))) break;
                int p = CAND - 1;
                while (p > 0 && (s > csm[p - 1] || (s == csm[p - 1] && id < cim[p - 1]))) {
                    csm[p] = csm[p - 1]; cim[p] = cim[p - 1]; --p;
                }
                csm[p] = s; cim[p] = id;
            }
        }
    }
    __syncthreads();

    // exact fp32 rescore; warp w handles candidates w, w+4, ...
    {
        int w = t >> 5, l = t & 31;
        for (int k = w; k < CAND; k += 4) {
            int id = cim[k];
            float sum = 0.f;
            if (id >= 0 && id < nkeys) {
                const float* row = mem + (size_t)id * DDIM;
#pragma unroll
                for (int d = l; d < DDIM; d += 32) sum = fmaf(qrow[d], row[d], sum);
            }
#pragma unroll
            for (int o = 16; o; o >>= 1) sum += __shfl_xor_sync(0xffffffffu, sum, o);
            if (l == 0) rs[k] = (id >= 0 && id < nkeys) ? sum : neg_inf();
        }
    }
    __syncthreads();

    if (t == 0) {
        float bs[TOPK]; int bi[TOPK];
#pragma unroll
        for (int i = 0; i < TOPK; ++i) { bs[i] = neg_inf(); bi[i] = 0x7fffffff; }
        for (int k = 0; k < CAND; ++k) {
            float s = rs[k]; int id = cim[k];
            if (s > bs[TOPK - 1] || (s == bs[TOPK - 1] && id < bi[TOPK - 1])) {
                float cs = s; int ci = id;
#pragma unroll
                for (int p = 0; p < TOPK; ++p) {
                    bool sw = (cs > bs[p]) || (cs == bs[p] && ci < bi[p]);
                    if (sw) { float ts = bs[p]; int ti = bi[p];
                              bs[p] = cs; bi[p] = ci; cs = ts; ci = ti; }
                }
            }
        }
#pragma unroll
        for (int i = 0; i < TOPK; ++i) { fs[i] = bs[i]; fi[i] = bi[i]; }
    }
    __syncthreads();

    if (t < TOPK) {
        out[q * TOPK + t]             = fs[t];
        out[NQ * TOPK + q * TOPK + t] = (float)fi[t];
    }
#pragma unroll 1
    for (int i = 0; i < TOPK; ++i) {
        int row = fi[i];
        size_t ob = (size_t)2 * NQ * TOPK + ((size_t)(q * TOPK + i)) * DDIM;
        out[ob + t]       = mem[(size_t)row * DDIM + t];
        out[ob + 128 + t] = mem[(size_t)row * DDIM + 128 + t];
    }
}

// =====================================================================
extern "C" void kernel_launch(void* const* d_in, const int* in_sizes, int n_in,
                              void* d_out, int out_size) {
    const float* hidden = (const float*)d_in[0];   // [64, 512]
    const float* Wp     = (const float*)d_in[1];   // [512, 1024]
    const float* bp     = (const float*)d_in[2];   // [1024]
    const float* mem    = (const float*)d_in[3];   // [N, 256]
    int nkeys  = in_sizes[3] / DDIM;
    int ntiles = (nkeys + BN - 1) / BN;

    proj_ln_kernel<<<256, 256>>>(hidden, Wp, bp);

    cudaFuncSetAttribute(score_kernel, cudaFuncAttributeMaxDynamicSharedMemorySize,
                         SMEM_SC);
    score_kernel<<<NCL, 256, SMEM_SC>>>(mem, nkeys, ntiles);

    merge_rescore_kernel<<<NQ, 128>>>(mem, (float*)d_out, nkeys);
}

// round 12
// speedup vs baseline: 1.0568x; 1.0527x over previous
#include <cuda_runtime.h>
#include <cuda_bf16.h>
#include <cstdint>

#define NUM_HEADS 4
#define DDIM      256
#define HID       512
#define NQ        256
#define TOPK      16
#define BN        128           // keys per score tile
#define NCTA      148           // persistent CTAs (1 per SM)
#define NCL       148           // candidate lists per query
#define CAND      40            // rescore candidate pool per query

// ---- score-phase dynamic smem layout (bytes) ----
#define A_OFF     0
#define A_BYTES   (256*512)             /* 256 q rows x 256 bf16 (swizzled) */
#define B_OFF     A_BYTES
#define B_STAGE   (128*80)              /* 128 keys x 32 bf16, rows padded to 80B */
#define S_OFF     (B_OFF + 2*B_STAGE)   /* 151552 */
#define S_STRIDE  67
#define SMEM_SC   (S_OFF + 256*S_STRIDE*4)  /* 220160 */

// ---- device scratch ----
__device__ __align__(16) float q_glob[NQ * DDIM];
__device__ float candS[(size_t)NQ * NCL * TOPK];
__device__ int   candI[(size_t)NQ * NCL * TOPK];
__device__ unsigned bar_ctr = 0;        // monotonic ticket barrier counter

__device__ __forceinline__ uint32_t smem_u32(const void* p) {
    uint32_t a;
    asm("{ .reg .u64 t; cvta.to.shared.u64 t, %1; cvt.u32.u64 %0, t; }" : "=r"(a) : "l"(p));
    return a;
}
__device__ __forceinline__ float neg_inf() { return __int_as_float(0xff800000); }

// grid-wide barrier: monotonic ticket (state returns consistent across graph
// replays; all NCTA CTAs are co-resident: grid 148 <= SM count, occupancy 1).
__device__ __forceinline__ void grid_barrier() {
    __syncthreads();
    if (threadIdx.x == 0) {
        __threadfence();
        unsigned ticket = atomicAdd(&bar_ctr, 1u);
        unsigned target = (ticket / NCTA + 1u) * NCTA;
        unsigned v;
        do {
            asm volatile("ld.acquire.gpu.u32 %0, [%1];" : "=r"(v) : "l"(&bar_ctr));
        } while (v < target);
        __threadfence();
    }
    __syncthreads();
}

#define LDSM_X4(r0,r1,r2,r3, addr) \
    asm volatile("ldmatrix.sync.aligned.m8n8.x4.shared.b16 {%0,%1,%2,%3}, [%4];" \
        : "=r"(r0), "=r"(r1), "=r"(r2), "=r"(r3) : "r"(addr))
#define MMA_BF16(d, a, b) \
    asm volatile("mma.sync.aligned.m16n8k16.row.col.f32.bf16.bf16.f32 " \
        "{%0,%1,%2,%3}, {%4,%5,%6,%7}, {%8,%9}, {%0,%1,%2,%3};" \
        : "+f"((d)[0]), "+f"((d)[1]), "+f"((d)[2]), "+f"((d)[3]) \
        : "r"((a)[0]), "r"((a)[1]), "r"((a)[2]), "r"((a)[3]), "r"((b)[0]), "r"((b)[1]))

__device__ __forceinline__ uint32_t pack_bf16x2(float lo, float hi) {
    __nv_bfloat162 h = __floats2bfloat162_rn(lo, hi);
    return *reinterpret_cast<uint32_t*>(&h);
}

// =====================================================================
// Single persistent kernel: proj+LN -> barrier -> score GEMM + top-16
// -> barrier -> merge + fp32 rescore + gather.
// grid = 148 CTAs x 256 threads, 220 KB dynamic smem.
// =====================================================================
__global__ void __launch_bounds__(256, 1)
retriever_fused(const float* __restrict__ hidden,
                const float* __restrict__ Wp,
                const float* __restrict__ bp,
                const float* __restrict__ mem,
                float* __restrict__ out,
                int nkeys, int ntiles) {
    extern __shared__ __align__(16) char smem[];
    uint32_t sb = smem_u32(smem);
    int bid = blockIdx.x;
    int tid = threadIdx.x, lane = tid & 31, wid = tid >> 5;

    // ================= Phase A: proj + layer_norm =================
    {
        float*  hid  = reinterpret_cast<float*>(smem);            // [512]
        float4* part = reinterpret_cast<float4*>(smem + 2048);    // [256]
        float*  red  = reinterpret_cast<float*>(smem + 6144);     // [4]
        const float4* W4 = reinterpret_cast<const float4*>(Wp);   // rows of 256 float4

        for (int task = bid; task < NQ; task += NCTA) {
            int b = task >> 2, h = task & 3;
            int cq = tid & 63, ks = tid >> 6;

            hid[tid]       = hidden[b * HID + tid];
            hid[tid + 256] = hidden[b * HID + 256 + tid];
            __syncthreads();

            float4 acc = make_float4(0.f, 0.f, 0.f, 0.f);
            int kbase = ks * 128;
#pragma unroll 8
            for (int k = 0; k < 128; ++k) {
                float4 w = W4[(size_t)(kbase + k) * 256 + h * 64 + cq];
                float hk = hid[kbase + k];
                acc.x = fmaf(hk, w.x, acc.x); acc.y = fmaf(hk, w.y, acc.y);
                acc.z = fmaf(hk, w.z, acc.z); acc.w = fmaf(hk, w.w, acc.w);
            }
            part[tid] = acc;
            __syncthreads();

            if (tid < 64) {
                float4 a0 = part[tid], a1 = part[64 + tid],
                       a2 = part[128 + tid], a3 = part[192 + tid];
                float4 bias = reinterpret_cast<const float4*>(bp)[h * 64 + tid];
                float4 x = make_float4(a0.x + a1.x + a2.x + a3.x + bias.x,
                                       a0.y + a1.y + a2.y + a3.y + bias.y,
                                       a0.z + a1.z + a2.z + a3.z + bias.z,
                                       a0.w + a1.w + a2.w + a3.w + bias.w);
                part[tid] = x;   // stash for after reduction
                float s1 = x.x + x.y + x.z + x.w;
                float s2 = x.x*x.x + x.y*x.y + x.z*x.z + x.w*x.w;
#pragma unroll
                for (int o = 16; o; o >>= 1) {
                    s1 += __shfl_xor_sync(0xffffffffu, s1, o);
                    s2 += __shfl_xor_sync(0xffffffffu, s2, o);
                }
                if (lane == 0) { red[tid >> 5] = s1; red[2 + (tid >> 5)] = s2; }
            }
            __syncthreads();
            if (tid < 64) {
                float hs1 = red[0] + red[1], hs2 = red[2] + red[3];
                float mean = hs1 * (1.0f / DDIM);
                float var  = hs2 * (1.0f / DDIM) - mean * mean;
                float r = rsqrtf(var + 1e-5f);
                float4 x = part[tid];
                float4 o4 = make_float4((x.x - mean) * r, (x.y - mean) * r,
                                        (x.z - mean) * r, (x.w - mean) * r);
                reinterpret_cast<float4*>(q_glob)[(size_t)(h * 64 + b) * 64 + tid] = o4;
            }
            __syncthreads();
        }
    }

    grid_barrier();   // q_glob complete

    // ================= Phase B: bf16 mma score GEMM + top-16 =================
    {
        int wm = wid & 3, wn = wid >> 2;

        // fill A (bf16, swizzled) from q_glob
#pragma unroll 4
        for (int idx = tid; idx < 256 * 128; idx += 256) {
            int m = idx >> 7, kp = idx & 127;
            float2 v = *reinterpret_cast<const float2*>(q_glob + m * DDIM + 2 * kp);
            uint32_t off = (uint32_t)(A_OFF + m * 512 + ((kp * 4) ^ ((m & 7) << 4)));
            *reinterpret_cast<uint32_t*>(smem + off) = pack_bf16x2(v.x, v.y);
        }
        __syncthreads();

        int ldrow = tid >> 1;
        int ldk   = (tid & 1) * 16;
        uint32_t sts_base = (uint32_t)(B_OFF + ldrow * 80 + (tid & 1) * 32);

        uint32_t a_rowbyte = (uint32_t)(A_OFF + (wm * 64 + (lane & 15)) * 512);
        uint32_t a_swz   = (uint32_t)((lane & 7) << 4);
        uint32_t a_koff2 = (uint32_t)((lane >> 4) * 16);
        int sub = lane >> 3;
        uint32_t b_lane = (uint32_t)(((wn * 64 + (sub >> 1) * 8 + (lane & 7)) * 80) +
                                     ((sub & 1) * 8) * 2);

        float topS[TOPK]; int topI[TOPK];
#pragma unroll
        for (int i = 0; i < TOPK; ++i) { topS[i] = neg_inf(); topI[i] = 0x7fffffff; }

        for (int tile = bid; tile < ntiles; tile += NCL) {
            int keybase = tile * BN;
            float acc[4][8][4];
#pragma unroll
            for (int mt = 0; mt < 4; ++mt)
#pragma unroll
                for (int nt = 0; nt < 8; ++nt)
#pragma unroll
                    for (int e = 0; e < 4; ++e) acc[mt][nt][e] = 0.f;

            float4 pf[4];
            {
                int key = keybase + ldrow;
                if (key < nkeys) {
                    const float4* src = reinterpret_cast<const float4*>(
                        mem + (size_t)key * DDIM + ldk);
#pragma unroll
                    for (int v = 0; v < 4; ++v) pf[v] = src[v];
                } else {
#pragma unroll
                    for (int v = 0; v < 4; ++v) pf[v] = make_float4(0.f, 0.f, 0.f, 0.f);
                }
            }

#pragma unroll 1
            for (int s = 0; s < 8; ++s) {
                int buf = s & 1;
                {
                    uint32_t u[8];
                    u[0] = pack_bf16x2(pf[0].x, pf[0].y); u[1] = pack_bf16x2(pf[0].z, pf[0].w);
                    u[2] = pack_bf16x2(pf[1].x, pf[1].y); u[3] = pack_bf16x2(pf[1].z, pf[1].w);
                    u[4] = pack_bf16x2(pf[2].x, pf[2].y); u[5] = pack_bf16x2(pf[2].z, pf[2].w);
                    u[6] = pack_bf16x2(pf[3].x, pf[3].y); u[7] = pack_bf16x2(pf[3].z, pf[3].w);
                    uint4* dst = reinterpret_cast<uint4*>(smem + sts_base + buf * B_STAGE);
                    dst[0] = make_uint4(u[0], u[1], u[2], u[3]);
                    dst[1] = make_uint4(u[4], u[5], u[6], u[7]);
                }
                __syncthreads();
                if (s < 7) {
                    int key = keybase + ldrow;
                    if (key < nkeys) {
                        const float4* src = reinterpret_cast<const float4*>(
                            mem + (size_t)key * DDIM + (s + 1) * 32 + ldk);
#pragma unroll
                        for (int v = 0; v < 4; ++v) pf[v] = src[v];
                    } else {
#pragma unroll
                        for (int v = 0; v < 4; ++v) pf[v] = make_float4(0.f, 0.f, 0.f, 0.f);
                    }
                }
                uint32_t bbuf = sb + (uint32_t)(B_OFF + buf * B_STAGE);
#pragma unroll
                for (int kk = 0; kk < 2; ++kk) {
                    uint32_t kbyte = (uint32_t)((s * 32 + kk * 16) * 2);
                    uint32_t a[4][4];
#pragma unroll
                    for (int mt = 0; mt < 4; ++mt)
                        LDSM_X4(a[mt][0], a[mt][1], a[mt][2], a[mt][3],
                                sb + a_rowbyte + (uint32_t)(mt * 8192) +
                                ((kbyte + a_koff2) ^ a_swz));
                    uint32_t b[8][2];
#pragma unroll
                    for (int p = 0; p < 4; ++p)
                        LDSM_X4(b[2*p][0], b[2*p][1], b[2*p+1][0], b[2*p+1][1],
                                bbuf + b_lane + (uint32_t)(p * 1280 + kk * 32));
#pragma unroll
                    for (int mt = 0; mt < 4; ++mt)
#pragma unroll
                        for (int nt = 0; nt < 8; ++nt)
                            MMA_BF16(acc[mt][nt], a[mt], b[nt]);
                }
            }

            // epilogue: two 64-col halves
            float* S = reinterpret_cast<float*>(smem + S_OFF);
#pragma unroll 1
            for (int half = 0; half < 2; ++half) {
                if (wn == half) {
#pragma unroll
                    for (int mt = 0; mt < 4; ++mt) {
                        int row = wm * 64 + mt * 16 + (lane >> 2);
#pragma unroll
                        for (int nt = 0; nt < 8; ++nt) {
                            int col = nt * 8 + (lane & 3) * 2;
                            S[row * S_STRIDE + col]           = acc[mt][nt][0];
                            S[row * S_STRIDE + col + 1]       = acc[mt][nt][1];
                            S[(row + 8) * S_STRIDE + col]     = acc[mt][nt][2];
                            S[(row + 8) * S_STRIDE + col + 1] = acc[mt][nt][3];
                        }
                    }
                }
                __syncthreads();
                int kb = keybase + half * 64;
                int jmax = nkeys - kb; if (jmax > 64) jmax = 64;
                const float* srow = S + tid * S_STRIDE;
                for (int j = 0; j < jmax; ++j) {
                    float sc = srow[j];
                    int key = kb + j;
                    if (sc > topS[TOPK - 1] ||
                        (sc == topS[TOPK - 1] && key < topI[TOPK - 1])) {
                        float cs = sc; int ci = key;
#pragma unroll
                        for (int p = 0; p < TOPK; ++p) {
                            bool sw = (cs > topS[p]) || (cs == topS[p] && ci < topI[p]);
                            if (sw) { float ts = topS[p]; int ti = topI[p];
                                      topS[p] = cs; topI[p] = ci; cs = ts; ci = ti; }
                        }
                    }
                }
                __syncthreads();
            }
        }

        // emit per-CTA sorted candidate list (thread = query)
        size_t base = ((size_t)tid * NCL + bid) * TOPK;
#pragma unroll
        for (int i = 0; i < TOPK; ++i) { candS[base + i] = topS[i]; candI[base + i] = topI[i]; }
    }

    grid_barrier();   // all candidates visible

    // ================= Phase C: merge + fp32 rescore + gather =================
    {
        float* ls   = reinterpret_cast<float*>(smem);                 // [32*16]
        int*   li   = reinterpret_cast<int*>(smem + 2048);            // [32*16]
        float* csm  = reinterpret_cast<float*>(smem + 4096);          // [CAND]
        int*   cim  = reinterpret_cast<int*>(smem + 4096 + 256);      // [CAND]
        float* qrow = reinterpret_cast<float*>(smem + 5120);          // [256]
        float* rs   = reinterpret_cast<float*>(smem + 6144);          // [CAND]
        float* fs   = reinterpret_cast<float*>(smem + 6400);          // [16]
        int*   fi   = reinterpret_cast<int*>(smem + 6464);            // [16]

        for (int q = bid; q < NQ; q += NCTA) {
            qrow[tid] = q_glob[q * DDIM + tid];
            __syncthreads();

            if (tid < 32) {
                float bs[TOPK]; int bi[TOPK];
#pragma unroll
                for (int i = 0; i < TOPK; ++i) { bs[i] = neg_inf(); bi[i] = 0x7fffffff; }
                for (int cl = tid; cl < NCL; cl += 32) {
                    size_t base = ((size_t)q * NCL + cl) * TOPK;
#pragma unroll 1
                    for (int i = 0; i < TOPK; ++i) {
                        float s = candS[base + i]; int id = candI[base + i];
                        if (!(s > bs[TOPK - 1] || (s == bs[TOPK - 1] && id < bi[TOPK - 1]))) break;
                        float cs = s; int ci = id;
#pragma unroll
                        for (int p = 0; p < TOPK; ++p) {
                            bool sw = (cs > bs[p]) || (cs == bs[p] && ci < bi[p]);
                            if (sw) { float ts = bs[p]; int ti = bi[p];
                                      bs[p] = cs; bi[p] = ci; cs = ts; ci = ti; }
                        }
                    }
                }
#pragma unroll
                for (int i = 0; i < TOPK; ++i) { ls[tid * TOPK + i] = bs[i]; li[tid * TOPK + i] = bi[i]; }
            }
            __syncthreads();

            if (tid == 0) {
                for (int i = 0; i < CAND; ++i) { csm[i] = neg_inf(); cim[i] = 0x7fffffff; }
                for (int l = 0; l < 32; ++l) {
#pragma unroll 1
                    for (int i = 0; i < TOPK; ++i) {
                        float s = ls[l * TOPK + i]; int id = li[l * TOPK + i];
                        if (!(s > csm[CAND - 1] || (s == csm[CAND - 1] && id < cim[CAND - 1]))) break;
                        int p = CAND - 1;
                        while (p > 0 && (s > csm[p - 1] || (s == csm[p - 1] && id < cim[p - 1]))) {
                            csm[p] = csm[p - 1]; cim[p] = cim[p - 1]; --p;
                        }
                        csm[p] = s; cim[p] = id;
                    }
                }
            }
            __syncthreads();

            // exact fp32 rescore; 8 warps, warp w handles candidates w, w+8, ...
            {
                for (int k = wid; k < CAND; k += 8) {
                    int id = cim[k];
                    float sum = 0.f;
                    if (id >= 0 && id < nkeys) {
                        const float* row = mem + (size_t)id * DDIM;
#pragma unroll
                        for (int d = lane; d < DDIM; d += 32) sum = fmaf(qrow[d], row[d], sum);
                    }
#pragma unroll
                    for (int o = 16; o; o >>= 1) sum += __shfl_xor_sync(0xffffffffu, sum, o);
                    if (lane == 0) rs[k] = (id >= 0 && id < nkeys) ? sum : neg_inf();
                }
            }
            __syncthreads();

            if (tid == 0) {
                float bs[TOPK]; int bi[TOPK];
#pragma unroll
                for (int i = 0; i < TOPK; ++i) { bs[i] = neg_inf(); bi[i] = 0x7fffffff; }
                for (int k = 0; k < CAND; ++k) {
                    float s = rs[k]; int id = cim[k];
                    if (s > bs[TOPK - 1] || (s == bs[TOPK - 1] && id < bi[TOPK - 1])) {
                        float cs = s; int ci = id;
#pragma unroll
                        for (int p = 0; p < TOPK; ++p) {
                            bool sw = (cs > bs[p]) || (cs == bs[p] && ci < bi[p]);
                            if (sw) { float ts = bs[p]; int ti = bi[p];
                                      bs[p] = cs; bi[p] = ci; cs = ts; ci = ti; }
                        }
                    }
                }
#pragma unroll
                for (int i = 0; i < TOPK; ++i) { fs[i] = bs[i]; fi[i] = bi[i]; }
            }
            __syncthreads();

            if (tid < TOPK) {
                out[q * TOPK + tid]             = fs[tid];
                out[NQ * TOPK + q * TOPK + tid] = (float)fi[tid];
            }
#pragma unroll 1
            for (int i = 0; i < TOPK; ++i) {
                int row = fi[i];
                size_t ob = (size_t)2 * NQ * TOPK + ((size_t)(q * TOPK + i)) * DDIM;
                out[ob + tid] = mem[(size_t)row * DDIM + tid];
            }
            __syncthreads();
        }
    }
}

// =====================================================================
extern "C" void kernel_launch(void* const* d_in, const int* in_sizes, int n_in,
                              void* d_out, int out_size) {
    const float* hidden = (const float*)d_in[0];   // [64, 512]
    const float* Wp     = (const float*)d_in[1];   // [512, 1024]
    const float* bp     = (const float*)d_in[2];   // [1024]
    const float* mem    = (const float*)d_in[3];   // [N, 256]
    int nkeys  = in_sizes[3] / DDIM;
    int ntiles = (nkeys + BN - 1) / BN;

    cudaFuncSetAttribute(retriever_fused, cudaFuncAttributeMaxDynamicSharedMemorySize,
                         SMEM_SC);
    retriever_fused<<<NCTA, 256, SMEM_SC>>>(hidden, Wp, bp, mem, (float*)d_out,
                                            nkeys, ntiles);
}